// round 8
// baseline (speedup 1.0000x reference)
#include <cuda_runtime.h>
#include <cuda_bf16.h>
#include <cstdint>

#define DEVI __device__ __forceinline__

constexpr int BB = 16;
constexpr int NN = 2048;
constexpr int CC = 512;
constexpr int DD = 64;
constexpr int MM = BB * NN;        // 32768
constexpr int NOUT = 2 * DD + CC;  // 640
constexpr float LOG2E = 1.4426950408889634f;

// ---------------- scratch (device globals; no runtime allocation) ----------------
__device__ __nv_bfloat16 g_xbf[(size_t)MM * CC];        // x in bf16  [B*N, C]
__device__ __nv_bfloat16 g_wall[(size_t)NOUT * CC];     // [Wq;Wk;Wv] rows, k-contig
__device__ float         g_ball[NOUT];                  // [bq;bk;bv]
__device__ __nv_bfloat16 g_qkv[(size_t)MM * NOUT];      // packed [M, 640]: Q(0:64)*log2e | K(64:128) | V(128:640)

// ---------------- PTX helpers ----------------
DEVI uint32_t smem_u32(const void* p) { return (uint32_t)__cvta_generic_to_shared(p); }

DEVI void cp16(uint32_t s, const void* g) {
    asm volatile("cp.async.cg.shared.global [%0], [%1], 16;\n" :: "r"(s), "l"(g));
}
DEVI void cp_commit() { asm volatile("cp.async.commit_group;\n" ::: "memory"); }
DEVI void cp_wait1()  { asm volatile("cp.async.wait_group 1;\n" ::: "memory"); }
DEVI void cp_wait0()  { asm volatile("cp.async.wait_group 0;\n" ::: "memory"); }

DEVI void ldm4(uint32_t r[4], uint32_t a) {
    asm volatile("ldmatrix.sync.aligned.m8n8.x4.shared.b16 {%0,%1,%2,%3}, [%4];\n"
        : "=r"(r[0]), "=r"(r[1]), "=r"(r[2]), "=r"(r[3]) : "r"(a));
}
DEVI void ldm4t(uint32_t r[4], uint32_t a) {
    asm volatile("ldmatrix.sync.aligned.m8n8.x4.trans.shared.b16 {%0,%1,%2,%3}, [%4];\n"
        : "=r"(r[0]), "=r"(r[1]), "=r"(r[2]), "=r"(r[3]) : "r"(a));
}

DEVI void mma16816(float d[4], const uint32_t a[4], uint32_t b0, uint32_t b1) {
    asm volatile(
        "mma.sync.aligned.m16n8k16.row.col.f32.bf16.bf16.f32 "
        "{%0,%1,%2,%3}, {%4,%5,%6,%7}, {%8,%9}, {%0,%1,%2,%3};\n"
        : "+f"(d[0]), "+f"(d[1]), "+f"(d[2]), "+f"(d[3])
        : "r"(a[0]), "r"(a[1]), "r"(a[2]), "r"(a[3]), "r"(b0), "r"(b1));
}

DEVI uint32_t packbf(float a, float b) {
    __nv_bfloat162 h = __floats2bfloat162_rn(a, b);
    return reinterpret_cast<uint32_t&>(h);
}
DEVI float ex2f(float x) { float r; asm("ex2.approx.f32 %0, %1;\n" : "=f"(r) : "f"(x)); return r; }

// ---------------- k0a: x -> bf16 ----------------
__global__ void k0_cvt_x(const float* __restrict__ x) {
    size_t i = ((size_t)blockIdx.x * blockDim.x + threadIdx.x) * 4;
    if (i < (size_t)MM * CC) {
        float4 v = *reinterpret_cast<const float4*>(x + i);
        __nv_bfloat162 p0 = __floats2bfloat162_rn(v.x, v.y);
        __nv_bfloat162 p1 = __floats2bfloat162_rn(v.z, v.w);
        *reinterpret_cast<__nv_bfloat162*>(&g_xbf[i])     = p0;
        *reinterpret_cast<__nv_bfloat162*>(&g_xbf[i + 2]) = p1;
    }
}

// ---------------- k0b: assemble Wall (bf16) + bias ----------------
__global__ void k0_cvt_w(const float* __restrict__ Wq, const float* __restrict__ bq,
                         const float* __restrict__ Wk, const float* __restrict__ bk,
                         const float* __restrict__ Wv, const float* __restrict__ bv) {
    int tid = blockIdx.x * blockDim.x + threadIdx.x;
    if (tid < NOUT * CC) {
        int j = tid >> 9, c = tid & 511;
        float v = (j < DD)     ? Wq[j * CC + c]
                : (j < 2 * DD) ? Wk[(j - DD) * CC + c]
                               : Wv[(size_t)(j - 2 * DD) * CC + c];
        g_wall[tid] = __float2bfloat16(v);
    }
    if (tid < NOUT) {
        g_ball[tid] = (tid < DD) ? bq[tid] : (tid < 2 * DD) ? bk[tid - DD] : bv[tid - 2 * DD];
    }
}

// ---------------- k1: QKV projection GEMM (128x128 tiles, BK=32, bf16 mma) ----------------
__global__ __launch_bounds__(256) void k1_qkv() {
    __shared__ __nv_bfloat16 As[2][128][40];
    __shared__ __nv_bfloat16 Bs[2][128][40];
    const int nt = blockIdx.x, mt = blockIdx.y;
    const int t = threadIdx.x, w = t >> 5, l = t & 31;
    const __nv_bfloat16* Ag = g_xbf  + (size_t)mt * 128 * CC;
    const __nv_bfloat16* Bg = g_wall + (size_t)nt * 128 * CC;

    float o[16][4];
    #pragma unroll
    for (int f = 0; f < 16; f++)
        #pragma unroll
        for (int r = 0; r < 4; r++) o[f][r] = 0.f;

    auto load = [&](int s, int kk) {
        #pragma unroll
        for (int i = 0; i < 2; i++) {
            int ci = t + 256 * i;
            int row = ci >> 2, c4 = ci & 3;
            cp16(smem_u32(&As[s][row][c4 * 8]), Ag + (size_t)row * CC + kk * 32 + c4 * 8);
        }
        #pragma unroll
        for (int i = 0; i < 2; i++) {
            int ci = t + 256 * i;
            int row = ci >> 2, c4 = ci & 3;
            cp16(smem_u32(&Bs[s][row][c4 * 8]), Bg + (size_t)row * CC + kk * 32 + c4 * 8);
        }
        cp_commit();
    };

    load(0, 0);
    for (int kk = 0; kk < 16; kk++) {
        int s = kk & 1;
        if (kk < 15) { load(s ^ 1, kk + 1); cp_wait1(); } else cp_wait0();
        __syncthreads();
        #pragma unroll
        for (int kd = 0; kd < 2; kd++) {
            uint32_t a[4];
            ldm4(a, smem_u32(&As[s][w * 16 + (l & 15)][kd * 16 + (l >> 4) * 8]));
            #pragma unroll
            for (int ng = 0; ng < 8; ng++) {
                uint32_t bm[4];
                ldm4(bm, smem_u32(&Bs[s][ng * 16 + (l & 15)][kd * 16 + (l >> 4) * 8]));
                mma16816(o[2 * ng],     a, bm[0], bm[2]);
                mma16816(o[2 * ng + 1], a, bm[1], bm[3]);
            }
        }
        __syncthreads();
    }

    // epilogue: bias (+log2e scale on Q) -> packed row-major [M, 640] bf16
    const int m0 = mt * 128 + w * 16 + (l >> 2);
    #pragma unroll
    for (int f = 0; f < 16; f++) {
        const int jj = nt * 128 + f * 8 + ((l & 3) << 1);
        const float b0 = g_ball[jj], b1 = g_ball[jj + 1];
        const float sc = (jj < DD) ? LOG2E : 1.0f;
        #pragma unroll
        for (int r = 0; r < 2; r++) {
            const int m = m0 + r * 8;
            const float v0 = (o[f][2 * r + 0] + b0) * sc;
            const float v1 = (o[f][2 * r + 1] + b1) * sc;
            __nv_bfloat162 pv = __floats2bfloat162_rn(v0, v1);
            *reinterpret_cast<__nv_bfloat162*>(&g_qkv[(size_t)m * NOUT + jj]) = pv;
        }
    }
}

// ---------------- k2: fused attention; 4 warps, warp = 32q x 128vcols ----------------
__global__ __launch_bounds__(128, 2) void k2_attn(const float* __restrict__ x,
                                                  float* __restrict__ out,
                                                  const float* __restrict__ gamma) {
    __shared__ __nv_bfloat16 Qs[128][72];
    __shared__ __nv_bfloat16 Ks[2][32][72];
    __shared__ __nv_bfloat16 Vs[2][32][136];
    const int vc = blockIdx.x, qt = blockIdx.y, b = blockIdx.z;
    const int t = threadIdx.x, w = t >> 5, l = t & 31;

    const __nv_bfloat16* Qg = g_qkv + (size_t)(b * NN + qt * 128) * NOUT;
    const __nv_bfloat16* Kg = g_qkv + (size_t)b * NN * NOUT + 64;
    const __nv_bfloat16* Vg = g_qkv + (size_t)b * NN * NOUT + 128 + vc * 128;

    // load Q tile: 128 rows x 64 cols (group 0)
    #pragma unroll
    for (int i = 0; i < 8; i++) {
        int ci = t + 128 * i;
        int row = ci >> 3, c8 = ci & 7;
        cp16(smem_u32(&Qs[row][c8 * 8]), Qg + (size_t)row * NOUT + c8 * 8);
    }
    cp_commit();

    auto load_kv = [&](int s, int kt) {
        #pragma unroll
        for (int i = 0; i < 2; i++) {       // K: 32 rows x 64
            int ci = t + 128 * i;
            int row = ci >> 3, c8 = ci & 7;
            cp16(smem_u32(&Ks[s][row][c8 * 8]), Kg + (size_t)(kt * 32 + row) * NOUT + c8 * 8);
        }
        #pragma unroll
        for (int i = 0; i < 4; i++) {       // V: 32 rows x 128
            int ci = t + 128 * i;
            int row = ci >> 4, c16 = ci & 15;
            cp16(smem_u32(&Vs[s][row][c16 * 8]), Vg + (size_t)(kt * 32 + row) * NOUT + c16 * 8);
        }
        cp_commit();
    };

    load_kv(0, 0);
    cp_wait1();          // Q group done
    __syncthreads();

    // Q fragments: 32 rows per warp, persistent in registers
    uint32_t qa[4][2][4];
    #pragma unroll
    for (int kd = 0; kd < 4; kd++)
        #pragma unroll
        for (int mi = 0; mi < 2; mi++)
            ldm4(qa[kd][mi], smem_u32(&Qs[w * 32 + mi * 16 + (l & 15)][kd * 16 + (l >> 4) * 8]));

    float o[2][16][4];
    #pragma unroll
    for (int mi = 0; mi < 2; mi++)
        #pragma unroll
        for (int f = 0; f < 16; f++)
            #pragma unroll
            for (int r = 0; r < 4; r++) o[mi][f][r] = 0.f;
    float rs[2][2] = {{0.f, 0.f}, {0.f, 0.f}};

    for (int kt = 0; kt < 64; kt++) {
        int s = kt & 1;
        if (kt < 63) { load_kv(s ^ 1, kt + 1); cp_wait1(); } else cp_wait0();
        __syncthreads();

        // S = Q K^T  (32 q-rows per warp x 32 keys); log2e pre-folded into Q
        float fs[2][4][4];
        #pragma unroll
        for (int mi = 0; mi < 2; mi++)
            #pragma unroll
            for (int f = 0; f < 4; f++)
                #pragma unroll
                for (int r = 0; r < 4; r++) fs[mi][f][r] = 0.f;
        #pragma unroll
        for (int kd = 0; kd < 4; kd++) {
            uint32_t k0[4], k1[4];
            ldm4(k0, smem_u32(&Ks[s][(l & 15)][kd * 16 + (l >> 4) * 8]));
            ldm4(k1, smem_u32(&Ks[s][16 + (l & 15)][kd * 16 + (l >> 4) * 8]));
            #pragma unroll
            for (int mi = 0; mi < 2; mi++) {
                mma16816(fs[mi][0], qa[kd][mi], k0[0], k0[2]);
                mma16816(fs[mi][1], qa[kd][mi], k0[1], k0[3]);
                mma16816(fs[mi][2], qa[kd][mi], k1[0], k1[2]);
                mma16816(fs[mi][3], qa[kd][mi], k1[1], k1[3]);
            }
        }

        // P = 2^S; rowsum accumulate; repack as A fragments for P@V
        uint32_t pa[2][2][4];
        #pragma unroll
        for (int mi = 0; mi < 2; mi++) {
            #pragma unroll
            for (int g = 0; g < 2; g++) {
                float e0[4], e1[4];
                #pragma unroll
                for (int r = 0; r < 4; r++) {
                    e0[r] = ex2f(fs[mi][2 * g][r]);
                    e1[r] = ex2f(fs[mi][2 * g + 1][r]);
                }
                rs[mi][0] += e0[0] + e0[1] + e1[0] + e1[1];
                rs[mi][1] += e0[2] + e0[3] + e1[2] + e1[3];
                pa[mi][g][0] = packbf(e0[0], e0[1]);
                pa[mi][g][1] = packbf(e0[2], e0[3]);
                pa[mi][g][2] = packbf(e1[0], e1[1]);
                pa[mi][g][3] = packbf(e1[2], e1[3]);
            }
        }

        // O += P @ V  (V row-major [keys][cols] via trans-ldmatrix)
        #pragma unroll
        for (int g = 0; g < 2; g++) {
            #pragma unroll
            for (int nc = 0; nc < 8; nc++) {
                uint32_t vb[4];
                ldm4t(vb, smem_u32(&Vs[s][g * 16 + (l & 15)][nc * 16 + (l >> 4) * 8]));
                #pragma unroll
                for (int mi = 0; mi < 2; mi++) {
                    mma16816(o[mi][2 * nc],     pa[mi][g], vb[0], vb[1]);
                    mma16816(o[mi][2 * nc + 1], pa[mi][g], vb[2], vb[3]);
                }
            }
        }
        __syncthreads();
    }

    // reduce rowsums across the 4 lanes sharing each row
    #pragma unroll
    for (int mi = 0; mi < 2; mi++) {
        rs[mi][0] += __shfl_xor_sync(0xffffffffu, rs[mi][0], 1);
        rs[mi][0] += __shfl_xor_sync(0xffffffffu, rs[mi][0], 2);
        rs[mi][1] += __shfl_xor_sync(0xffffffffu, rs[mi][1], 1);
        rs[mi][1] += __shfl_xor_sync(0xffffffffu, rs[mi][1], 2);
    }
    const float gm = gamma[0];

    // epilogue: out = gamma * O / rowsum + x   ([B, N, C] fp32)
    #pragma unroll
    for (int mi = 0; mi < 2; mi++) {
        const float i0 = gm / rs[mi][0], i1 = gm / rs[mi][1];
        const int q0 = qt * 128 + w * 32 + mi * 16 + (l >> 2);
        const size_t base = ((size_t)(b * NN + q0)) * CC + vc * 128;
        #pragma unroll
        for (int f = 0; f < 16; f++) {
            const int n = f * 8 + ((l & 3) << 1);
            float2 xr0 = *reinterpret_cast<const float2*>(&x[base + n]);
            float2 ov0 = make_float2(o[mi][f][0] * i0 + xr0.x, o[mi][f][1] * i0 + xr0.y);
            *reinterpret_cast<float2*>(&out[base + n]) = ov0;
            float2 xr1 = *reinterpret_cast<const float2*>(&x[base + 8 * CC + n]);
            float2 ov1 = make_float2(o[mi][f][2] * i1 + xr1.x, o[mi][f][3] * i1 + xr1.y);
            *reinterpret_cast<float2*>(&out[base + 8 * CC + n]) = ov1;
        }
    }
}

// ---------------- launch ----------------
extern "C" void kernel_launch(void* const* d_in, const int* in_sizes, int n_in,
                              void* d_out, int out_size) {
    (void)in_sizes; (void)n_in; (void)out_size;
    const float* x     = (const float*)d_in[0];
    const float* Wq    = (const float*)d_in[1];
    const float* bq    = (const float*)d_in[2];
    const float* Wk    = (const float*)d_in[3];
    const float* bk    = (const float*)d_in[4];
    const float* Wv    = (const float*)d_in[5];
    const float* bv    = (const float*)d_in[6];
    const float* gamma = (const float*)d_in[7];
    float* out = (float*)d_out;

    k0_cvt_x<<<(int)(((size_t)MM * CC / 4 + 255) / 256), 256>>>(x);
    k0_cvt_w<<<(NOUT * CC + 255) / 256, 256>>>(Wq, bq, Wk, bk, Wv, bv);
    k1_qkv<<<dim3(NOUT / 128, MM / 128), 256>>>();
    k2_attn<<<dim3(CC / 128, NN / 128, BB), 128>>>(x, out, gamma);
}

// round 9
// speedup vs baseline: 1.0023x; 1.0023x over previous
#include <cuda_runtime.h>
#include <cuda_bf16.h>
#include <cstdint>

#define DEVI __device__ __forceinline__

constexpr int BB = 16;
constexpr int NN = 2048;
constexpr int CC = 512;
constexpr int DD = 64;
constexpr int MM = BB * NN;        // 32768
constexpr int NOUT = 2 * DD + CC;  // 640
constexpr float LOG2E = 1.4426950408889634f;

// ---------------- scratch (device globals; no runtime allocation) ----------------
__device__ __nv_bfloat16 g_xbf[(size_t)MM * CC];        // x in bf16  [B*N, C]
__device__ __nv_bfloat16 g_wall[(size_t)NOUT * CC];     // [Wq;Wk;Wv] rows, k-contig
__device__ float         g_ball[NOUT];                  // [bq;bk;bv]
__device__ __nv_bfloat16 g_qkv[(size_t)MM * NOUT];      // packed [M, 640]: Q(0:64)*log2e | K(64:128) | V(128:640)

// ---------------- PTX helpers ----------------
DEVI uint32_t smem_u32(const void* p) { return (uint32_t)__cvta_generic_to_shared(p); }

DEVI void cp16(uint32_t s, const void* g) {
    asm volatile("cp.async.cg.shared.global [%0], [%1], 16;\n" :: "r"(s), "l"(g));
}
DEVI void cp_commit() { asm volatile("cp.async.commit_group;\n" ::: "memory"); }
DEVI void cp_wait1()  { asm volatile("cp.async.wait_group 1;\n" ::: "memory"); }
DEVI void cp_wait0()  { asm volatile("cp.async.wait_group 0;\n" ::: "memory"); }

DEVI void ldm4(uint32_t r[4], uint32_t a) {
    asm volatile("ldmatrix.sync.aligned.m8n8.x4.shared.b16 {%0,%1,%2,%3}, [%4];\n"
        : "=r"(r[0]), "=r"(r[1]), "=r"(r[2]), "=r"(r[3]) : "r"(a));
}
DEVI void ldm4t(uint32_t r[4], uint32_t a) {
    asm volatile("ldmatrix.sync.aligned.m8n8.x4.trans.shared.b16 {%0,%1,%2,%3}, [%4];\n"
        : "=r"(r[0]), "=r"(r[1]), "=r"(r[2]), "=r"(r[3]) : "r"(a));
}

DEVI void mma16816(float d[4], const uint32_t a[4], uint32_t b0, uint32_t b1) {
    asm volatile(
        "mma.sync.aligned.m16n8k16.row.col.f32.bf16.bf16.f32 "
        "{%0,%1,%2,%3}, {%4,%5,%6,%7}, {%8,%9}, {%0,%1,%2,%3};\n"
        : "+f"(d[0]), "+f"(d[1]), "+f"(d[2]), "+f"(d[3])
        : "r"(a[0]), "r"(a[1]), "r"(a[2]), "r"(a[3]), "r"(b0), "r"(b1));
}

DEVI uint32_t packbf(float a, float b) {
    __nv_bfloat162 h = __floats2bfloat162_rn(a, b);
    return reinterpret_cast<uint32_t&>(h);
}
DEVI float ex2f(float x) { float r; asm("ex2.approx.f32 %0, %1;\n" : "=f"(r) : "f"(x)); return r; }

// ---------------- k0a: x -> bf16 ----------------
__global__ void k0_cvt_x(const float* __restrict__ x) {
    size_t i = ((size_t)blockIdx.x * blockDim.x + threadIdx.x) * 4;
    if (i < (size_t)MM * CC) {
        float4 v = *reinterpret_cast<const float4*>(x + i);
        __nv_bfloat162 p0 = __floats2bfloat162_rn(v.x, v.y);
        __nv_bfloat162 p1 = __floats2bfloat162_rn(v.z, v.w);
        *reinterpret_cast<__nv_bfloat162*>(&g_xbf[i])     = p0;
        *reinterpret_cast<__nv_bfloat162*>(&g_xbf[i + 2]) = p1;
    }
}

// ---------------- k0b: assemble Wall (bf16) + bias ----------------
__global__ void k0_cvt_w(const float* __restrict__ Wq, const float* __restrict__ bq,
                         const float* __restrict__ Wk, const float* __restrict__ bk,
                         const float* __restrict__ Wv, const float* __restrict__ bv) {
    int tid = blockIdx.x * blockDim.x + threadIdx.x;
    if (tid < NOUT * CC) {
        int j = tid >> 9, c = tid & 511;
        float v = (j < DD)     ? Wq[j * CC + c]
                : (j < 2 * DD) ? Wk[(j - DD) * CC + c]
                               : Wv[(size_t)(j - 2 * DD) * CC + c];
        g_wall[tid] = __float2bfloat16(v);
    }
    if (tid < NOUT) {
        g_ball[tid] = (tid < DD) ? bq[tid] : (tid < 2 * DD) ? bk[tid - DD] : bv[tid - 2 * DD];
    }
}

// ---------------- k1: QKV projection GEMM (128x128 tiles, BK=32, bf16 mma) ----------------
__global__ __launch_bounds__(256) void k1_qkv() {
    __shared__ __nv_bfloat16 As[2][128][40];
    __shared__ __nv_bfloat16 Bs[2][128][40];
    const int nt = blockIdx.x, mt = blockIdx.y;
    const int t = threadIdx.x, w = t >> 5, l = t & 31;
    const __nv_bfloat16* Ag = g_xbf  + (size_t)mt * 128 * CC;
    const __nv_bfloat16* Bg = g_wall + (size_t)nt * 128 * CC;

    float o[16][4];
    #pragma unroll
    for (int f = 0; f < 16; f++)
        #pragma unroll
        for (int r = 0; r < 4; r++) o[f][r] = 0.f;

    auto load = [&](int s, int kk) {
        #pragma unroll
        for (int i = 0; i < 2; i++) {
            int ci = t + 256 * i;
            int row = ci >> 2, c4 = ci & 3;
            cp16(smem_u32(&As[s][row][c4 * 8]), Ag + (size_t)row * CC + kk * 32 + c4 * 8);
        }
        #pragma unroll
        for (int i = 0; i < 2; i++) {
            int ci = t + 256 * i;
            int row = ci >> 2, c4 = ci & 3;
            cp16(smem_u32(&Bs[s][row][c4 * 8]), Bg + (size_t)row * CC + kk * 32 + c4 * 8);
        }
        cp_commit();
    };

    load(0, 0);
    for (int kk = 0; kk < 16; kk++) {
        int s = kk & 1;
        if (kk < 15) { load(s ^ 1, kk + 1); cp_wait1(); } else cp_wait0();
        __syncthreads();
        #pragma unroll
        for (int kd = 0; kd < 2; kd++) {
            uint32_t a[4];
            ldm4(a, smem_u32(&As[s][w * 16 + (l & 15)][kd * 16 + (l >> 4) * 8]));
            #pragma unroll
            for (int ng = 0; ng < 8; ng++) {
                uint32_t bm[4];
                ldm4(bm, smem_u32(&Bs[s][ng * 16 + (l & 15)][kd * 16 + (l >> 4) * 8]));
                mma16816(o[2 * ng],     a, bm[0], bm[2]);
                mma16816(o[2 * ng + 1], a, bm[1], bm[3]);
            }
        }
        __syncthreads();
    }

    // epilogue: bias (+log2e scale on Q) -> packed row-major [M, 640] bf16
    const int m0 = mt * 128 + w * 16 + (l >> 2);
    #pragma unroll
    for (int f = 0; f < 16; f++) {
        const int jj = nt * 128 + f * 8 + ((l & 3) << 1);
        const float b0 = g_ball[jj], b1 = g_ball[jj + 1];
        const float sc = (jj < DD) ? LOG2E : 1.0f;
        #pragma unroll
        for (int r = 0; r < 2; r++) {
            const int m = m0 + r * 8;
            const float v0 = (o[f][2 * r + 0] + b0) * sc;
            const float v1 = (o[f][2 * r + 1] + b1) * sc;
            __nv_bfloat162 pv = __floats2bfloat162_rn(v0, v1);
            *reinterpret_cast<__nv_bfloat162*>(&g_qkv[(size_t)m * NOUT + jj]) = pv;
        }
    }
}

// ---------------- k2: fused attention; 4 warps, warp = 32q x 128vcols ----------------
__global__ __launch_bounds__(128, 2) void k2_attn(const float* __restrict__ x,
                                                  float* __restrict__ out,
                                                  const float* __restrict__ gamma) {
    __shared__ __nv_bfloat16 Qs[128][72];
    __shared__ __nv_bfloat16 Ks[2][32][72];
    __shared__ __nv_bfloat16 Vs[2][32][136];
    const int vc = blockIdx.x, qt = blockIdx.y, b = blockIdx.z;
    const int t = threadIdx.x, w = t >> 5, l = t & 31;

    const __nv_bfloat16* Qg = g_qkv + (size_t)(b * NN + qt * 128) * NOUT;
    const __nv_bfloat16* Kg = g_qkv + (size_t)b * NN * NOUT + 64;
    const __nv_bfloat16* Vg = g_qkv + (size_t)b * NN * NOUT + 128 + vc * 128;

    // load Q tile: 128 rows x 64 cols (group 0)
    #pragma unroll
    for (int i = 0; i < 8; i++) {
        int ci = t + 128 * i;
        int row = ci >> 3, c8 = ci & 7;
        cp16(smem_u32(&Qs[row][c8 * 8]), Qg + (size_t)row * NOUT + c8 * 8);
    }
    cp_commit();

    auto load_kv = [&](int s, int kt) {
        #pragma unroll
        for (int i = 0; i < 2; i++) {       // K: 32 rows x 64
            int ci = t + 128 * i;
            int row = ci >> 3, c8 = ci & 7;
            cp16(smem_u32(&Ks[s][row][c8 * 8]), Kg + (size_t)(kt * 32 + row) * NOUT + c8 * 8);
        }
        #pragma unroll
        for (int i = 0; i < 4; i++) {       // V: 32 rows x 128
            int ci = t + 128 * i;
            int row = ci >> 4, c16 = ci & 15;
            cp16(smem_u32(&Vs[s][row][c16 * 8]), Vg + (size_t)(kt * 32 + row) * NOUT + c16 * 8);
        }
        cp_commit();
    };

    load_kv(0, 0);
    cp_wait1();          // Q group done
    __syncthreads();

    // Q fragments: 32 rows per warp, persistent in registers
    uint32_t qa[4][2][4];
    #pragma unroll
    for (int kd = 0; kd < 4; kd++)
        #pragma unroll
        for (int mi = 0; mi < 2; mi++)
            ldm4(qa[kd][mi], smem_u32(&Qs[w * 32 + mi * 16 + (l & 15)][kd * 16 + (l >> 4) * 8]));

    float o[2][16][4];
    #pragma unroll
    for (int mi = 0; mi < 2; mi++)
        #pragma unroll
        for (int f = 0; f < 16; f++)
            #pragma unroll
            for (int r = 0; r < 4; r++) o[mi][f][r] = 0.f;
    float rs[2][2] = {{0.f, 0.f}, {0.f, 0.f}};

    for (int kt = 0; kt < 64; kt++) {
        int s = kt & 1;
        if (kt < 63) { load_kv(s ^ 1, kt + 1); cp_wait1(); } else cp_wait0();
        __syncthreads();

        // S = Q K^T  (32 q-rows per warp x 32 keys); log2e pre-folded into Q
        float fs[2][4][4];
        #pragma unroll
        for (int mi = 0; mi < 2; mi++)
            #pragma unroll
            for (int f = 0; f < 4; f++)
                #pragma unroll
                for (int r = 0; r < 4; r++) fs[mi][f][r] = 0.f;
        #pragma unroll
        for (int kd = 0; kd < 4; kd++) {
            uint32_t k0[4], k1[4];
            ldm4(k0, smem_u32(&Ks[s][(l & 15)][kd * 16 + (l >> 4) * 8]));
            ldm4(k1, smem_u32(&Ks[s][16 + (l & 15)][kd * 16 + (l >> 4) * 8]));
            #pragma unroll
            for (int mi = 0; mi < 2; mi++) {
                mma16816(fs[mi][0], qa[kd][mi], k0[0], k0[2]);
                mma16816(fs[mi][1], qa[kd][mi], k0[1], k0[3]);
                mma16816(fs[mi][2], qa[kd][mi], k1[0], k1[2]);
                mma16816(fs[mi][3], qa[kd][mi], k1[1], k1[3]);
            }
        }

        // P = 2^S; rowsum accumulate; repack as A fragments for P@V
        uint32_t pa[2][2][4];
        #pragma unroll
        for (int mi = 0; mi < 2; mi++) {
            #pragma unroll
            for (int g = 0; g < 2; g++) {
                float e0[4], e1[4];
                #pragma unroll
                for (int r = 0; r < 4; r++) {
                    e0[r] = ex2f(fs[mi][2 * g][r]);
                    e1[r] = ex2f(fs[mi][2 * g + 1][r]);
                }
                rs[mi][0] += e0[0] + e0[1] + e1[0] + e1[1];
                rs[mi][1] += e0[2] + e0[3] + e1[2] + e1[3];
                pa[mi][g][0] = packbf(e0[0], e0[1]);
                pa[mi][g][1] = packbf(e0[2], e0[3]);
                pa[mi][g][2] = packbf(e1[0], e1[1]);
                pa[mi][g][3] = packbf(e1[2], e1[3]);
            }
        }

        // O += P @ V  (V row-major [keys][cols] via trans-ldmatrix)
        #pragma unroll
        for (int g = 0; g < 2; g++) {
            #pragma unroll
            for (int nc = 0; nc < 8; nc++) {
                uint32_t vb[4];
                ldm4t(vb, smem_u32(&Vs[s][g * 16 + (l & 15)][nc * 16 + (l >> 4) * 8]));
                #pragma unroll
                for (int mi = 0; mi < 2; mi++) {
                    mma16816(o[mi][2 * nc],     pa[mi][g], vb[0], vb[1]);
                    mma16816(o[mi][2 * nc + 1], pa[mi][g], vb[2], vb[3]);
                }
            }
        }
        __syncthreads();
    }

    // reduce rowsums across the 4 lanes sharing each row
    #pragma unroll
    for (int mi = 0; mi < 2; mi++) {
        rs[mi][0] += __shfl_xor_sync(0xffffffffu, rs[mi][0], 1);
        rs[mi][0] += __shfl_xor_sync(0xffffffffu, rs[mi][0], 2);
        rs[mi][1] += __shfl_xor_sync(0xffffffffu, rs[mi][1], 1);
        rs[mi][1] += __shfl_xor_sync(0xffffffffu, rs[mi][1], 2);
    }
    const float gm = gamma[0];

    // epilogue: out = gamma * O / rowsum + x   ([B, N, C] fp32)
    #pragma unroll
    for (int mi = 0; mi < 2; mi++) {
        const float i0 = gm / rs[mi][0], i1 = gm / rs[mi][1];
        const int q0 = qt * 128 + w * 32 + mi * 16 + (l >> 2);
        const size_t base = ((size_t)(b * NN + q0)) * CC + vc * 128;
        #pragma unroll
        for (int f = 0; f < 16; f++) {
            const int n = f * 8 + ((l & 3) << 1);
            float2 xr0 = *reinterpret_cast<const float2*>(&x[base + n]);
            float2 ov0 = make_float2(o[mi][f][0] * i0 + xr0.x, o[mi][f][1] * i0 + xr0.y);
            *reinterpret_cast<float2*>(&out[base + n]) = ov0;
            float2 xr1 = *reinterpret_cast<const float2*>(&x[base + 8 * CC + n]);
            float2 ov1 = make_float2(o[mi][f][2] * i1 + xr1.x, o[mi][f][3] * i1 + xr1.y);
            *reinterpret_cast<float2*>(&out[base + 8 * CC + n]) = ov1;
        }
    }
}

// ---------------- launch ----------------
extern "C" void kernel_launch(void* const* d_in, const int* in_sizes, int n_in,
                              void* d_out, int out_size) {
    (void)in_sizes; (void)n_in; (void)out_size;
    const float* x     = (const float*)d_in[0];
    const float* Wq    = (const float*)d_in[1];
    const float* bq    = (const float*)d_in[2];
    const float* Wk    = (const float*)d_in[3];
    const float* bk    = (const float*)d_in[4];
    const float* Wv    = (const float*)d_in[5];
    const float* bv    = (const float*)d_in[6];
    const float* gamma = (const float*)d_in[7];
    float* out = (float*)d_out;

    k0_cvt_x<<<(int)(((size_t)MM * CC / 4 + 255) / 256), 256>>>(x);
    k0_cvt_w<<<(NOUT * CC + 255) / 256, 256>>>(Wq, bq, Wk, bk, Wv, bv);
    k1_qkv<<<dim3(NOUT / 128, MM / 128), 256>>>();
    k2_attn<<<dim3(CC / 128, NN / 128, BB), 128>>>(x, out, gamma);
}

// round 10
// speedup vs baseline: 1.0039x; 1.0016x over previous
#include <cuda_runtime.h>
#include <cuda_bf16.h>
#include <cstdint>

#define DEVI __device__ __forceinline__

constexpr int BB = 16;
constexpr int NN = 2048;
constexpr int CC = 512;
constexpr int DD = 64;
constexpr int MM = BB * NN;        // 32768
constexpr int NOUT = 2 * DD + CC;  // 640
constexpr float LOG2E = 1.4426950408889634f;

// ---------------- scratch (device globals; no runtime allocation) ----------------
__device__ __nv_bfloat16 g_xbf[(size_t)MM * CC];        // x in bf16  [B*N, C]
__device__ __nv_bfloat16 g_wall[(size_t)NOUT * CC];     // [Wq;Wk;Wv] rows, k-contig
__device__ float         g_ball[NOUT];                  // [bq;bk;bv]
__device__ __nv_bfloat16 g_qkv[(size_t)MM * NOUT];      // packed [M, 640]: Q(0:64)*log2e | K(64:128) | V(128:640)

// ---------------- PTX helpers ----------------
DEVI uint32_t smem_u32(const void* p) { return (uint32_t)__cvta_generic_to_shared(p); }

DEVI void cp16(uint32_t s, const void* g) {
    asm volatile("cp.async.cg.shared.global [%0], [%1], 16;\n" :: "r"(s), "l"(g));
}
DEVI void cp_commit() { asm volatile("cp.async.commit_group;\n" ::: "memory"); }
DEVI void cp_wait1()  { asm volatile("cp.async.wait_group 1;\n" ::: "memory"); }
DEVI void cp_wait0()  { asm volatile("cp.async.wait_group 0;\n" ::: "memory"); }

DEVI void ldm4(uint32_t r[4], uint32_t a) {
    asm volatile("ldmatrix.sync.aligned.m8n8.x4.shared.b16 {%0,%1,%2,%3}, [%4];\n"
        : "=r"(r[0]), "=r"(r[1]), "=r"(r[2]), "=r"(r[3]) : "r"(a));
}
DEVI void ldm4t(uint32_t r[4], uint32_t a) {
    asm volatile("ldmatrix.sync.aligned.m8n8.x4.trans.shared.b16 {%0,%1,%2,%3}, [%4];\n"
        : "=r"(r[0]), "=r"(r[1]), "=r"(r[2]), "=r"(r[3]) : "r"(a));
}

DEVI void mma16816(float d[4], const uint32_t a[4], uint32_t b0, uint32_t b1) {
    asm volatile(
        "mma.sync.aligned.m16n8k16.row.col.f32.bf16.bf16.f32 "
        "{%0,%1,%2,%3}, {%4,%5,%6,%7}, {%8,%9}, {%0,%1,%2,%3};\n"
        : "+f"(d[0]), "+f"(d[1]), "+f"(d[2]), "+f"(d[3])
        : "r"(a[0]), "r"(a[1]), "r"(a[2]), "r"(a[3]), "r"(b0), "r"(b1));
}

DEVI uint32_t packbf(float a, float b) {
    __nv_bfloat162 h = __floats2bfloat162_rn(a, b);
    return reinterpret_cast<uint32_t&>(h);
}
DEVI float ex2f(float x) { float r; asm("ex2.approx.f32 %0, %1;\n" : "=f"(r) : "f"(x)); return r; }

// ---------------- k0a: x -> bf16 ----------------
__global__ void k0_cvt_x(const float* __restrict__ x) {
    size_t i = ((size_t)blockIdx.x * blockDim.x + threadIdx.x) * 4;
    if (i < (size_t)MM * CC) {
        float4 v = *reinterpret_cast<const float4*>(x + i);
        __nv_bfloat162 p0 = __floats2bfloat162_rn(v.x, v.y);
        __nv_bfloat162 p1 = __floats2bfloat162_rn(v.z, v.w);
        *reinterpret_cast<__nv_bfloat162*>(&g_xbf[i])     = p0;
        *reinterpret_cast<__nv_bfloat162*>(&g_xbf[i + 2]) = p1;
    }
}

// ---------------- k0b: assemble Wall (bf16) + bias ----------------
__global__ void k0_cvt_w(const float* __restrict__ Wq, const float* __restrict__ bq,
                         const float* __restrict__ Wk, const float* __restrict__ bk,
                         const float* __restrict__ Wv, const float* __restrict__ bv) {
    int tid = blockIdx.x * blockDim.x + threadIdx.x;
    if (tid < NOUT * CC) {
        int j = tid >> 9, c = tid & 511;
        float v = (j < DD)     ? Wq[j * CC + c]
                : (j < 2 * DD) ? Wk[(j - DD) * CC + c]
                               : Wv[(size_t)(j - 2 * DD) * CC + c];
        g_wall[tid] = __float2bfloat16(v);
    }
    if (tid < NOUT) {
        g_ball[tid] = (tid < DD) ? bq[tid] : (tid < 2 * DD) ? bk[tid - DD] : bv[tid - 2 * DD];
    }
}

// ---------------- k1: QKV projection GEMM (128x128 tiles, BK=32, bf16 mma) ----------------
__global__ __launch_bounds__(256) void k1_qkv() {
    __shared__ __nv_bfloat16 As[2][128][40];
    __shared__ __nv_bfloat16 Bs[2][128][40];
    const int nt = blockIdx.x, mt = blockIdx.y;
    const int t = threadIdx.x, w = t >> 5, l = t & 31;
    const __nv_bfloat16* Ag = g_xbf  + (size_t)mt * 128 * CC;
    const __nv_bfloat16* Bg = g_wall + (size_t)nt * 128 * CC;

    float o[16][4];
    #pragma unroll
    for (int f = 0; f < 16; f++)
        #pragma unroll
        for (int r = 0; r < 4; r++) o[f][r] = 0.f;

    auto load = [&](int s, int kk) {
        #pragma unroll
        for (int i = 0; i < 2; i++) {
            int ci = t + 256 * i;
            int row = ci >> 2, c4 = ci & 3;
            cp16(smem_u32(&As[s][row][c4 * 8]), Ag + (size_t)row * CC + kk * 32 + c4 * 8);
        }
        #pragma unroll
        for (int i = 0; i < 2; i++) {
            int ci = t + 256 * i;
            int row = ci >> 2, c4 = ci & 3;
            cp16(smem_u32(&Bs[s][row][c4 * 8]), Bg + (size_t)row * CC + kk * 32 + c4 * 8);
        }
        cp_commit();
    };

    load(0, 0);
    for (int kk = 0; kk < 16; kk++) {
        int s = kk & 1;
        if (kk < 15) { load(s ^ 1, kk + 1); cp_wait1(); } else cp_wait0();
        __syncthreads();
        #pragma unroll
        for (int kd = 0; kd < 2; kd++) {
            uint32_t a[4];
            ldm4(a, smem_u32(&As[s][w * 16 + (l & 15)][kd * 16 + (l >> 4) * 8]));
            #pragma unroll
            for (int ng = 0; ng < 8; ng++) {
                uint32_t bm[4];
                ldm4(bm, smem_u32(&Bs[s][ng * 16 + (l & 15)][kd * 16 + (l >> 4) * 8]));
                mma16816(o[2 * ng],     a, bm[0], bm[2]);
                mma16816(o[2 * ng + 1], a, bm[1], bm[3]);
            }
        }
        __syncthreads();
    }

    // epilogue: bias (+log2e scale on Q) -> packed row-major [M, 640] bf16
    const int m0 = mt * 128 + w * 16 + (l >> 2);
    #pragma unroll
    for (int f = 0; f < 16; f++) {
        const int jj = nt * 128 + f * 8 + ((l & 3) << 1);
        const float b0 = g_ball[jj], b1 = g_ball[jj + 1];
        const float sc = (jj < DD) ? LOG2E : 1.0f;
        #pragma unroll
        for (int r = 0; r < 2; r++) {
            const int m = m0 + r * 8;
            const float v0 = (o[f][2 * r + 0] + b0) * sc;
            const float v1 = (o[f][2 * r + 1] + b1) * sc;
            __nv_bfloat162 pv = __floats2bfloat162_rn(v0, v1);
            *reinterpret_cast<__nv_bfloat162*>(&g_qkv[(size_t)m * NOUT + jj]) = pv;
        }
    }
}

// ---------------- k2: fused attention; 4 warps, warp = 32q x 128vcols ----------------
__global__ __launch_bounds__(128, 2) void k2_attn(const float* __restrict__ x,
                                                  float* __restrict__ out,
                                                  const float* __restrict__ gamma) {
    __shared__ __nv_bfloat16 Qs[128][72];
    __shared__ __nv_bfloat16 Ks[2][32][72];
    __shared__ __nv_bfloat16 Vs[2][32][136];
    const int vc = blockIdx.x, qt = blockIdx.y, b = blockIdx.z;
    const int t = threadIdx.x, w = t >> 5, l = t & 31;

    const __nv_bfloat16* Qg = g_qkv + (size_t)(b * NN + qt * 128) * NOUT;
    const __nv_bfloat16* Kg = g_qkv + (size_t)b * NN * NOUT + 64;
    const __nv_bfloat16* Vg = g_qkv + (size_t)b * NN * NOUT + 128 + vc * 128;

    // load Q tile: 128 rows x 64 cols (group 0)
    #pragma unroll
    for (int i = 0; i < 8; i++) {
        int ci = t + 128 * i;
        int row = ci >> 3, c8 = ci & 7;
        cp16(smem_u32(&Qs[row][c8 * 8]), Qg + (size_t)row * NOUT + c8 * 8);
    }
    cp_commit();

    auto load_kv = [&](int s, int kt) {
        #pragma unroll
        for (int i = 0; i < 2; i++) {       // K: 32 rows x 64
            int ci = t + 128 * i;
            int row = ci >> 3, c8 = ci & 7;
            cp16(smem_u32(&Ks[s][row][c8 * 8]), Kg + (size_t)(kt * 32 + row) * NOUT + c8 * 8);
        }
        #pragma unroll
        for (int i = 0; i < 4; i++) {       // V: 32 rows x 128
            int ci = t + 128 * i;
            int row = ci >> 4, c16 = ci & 15;
            cp16(smem_u32(&Vs[s][row][c16 * 8]), Vg + (size_t)(kt * 32 + row) * NOUT + c16 * 8);
        }
        cp_commit();
    };

    load_kv(0, 0);
    cp_wait1();          // Q group done
    __syncthreads();

    // Q fragments: 32 rows per warp, persistent in registers
    uint32_t qa[4][2][4];
    #pragma unroll
    for (int kd = 0; kd < 4; kd++)
        #pragma unroll
        for (int mi = 0; mi < 2; mi++)
            ldm4(qa[kd][mi], smem_u32(&Qs[w * 32 + mi * 16 + (l & 15)][kd * 16 + (l >> 4) * 8]));

    float o[2][16][4];
    #pragma unroll
    for (int mi = 0; mi < 2; mi++)
        #pragma unroll
        for (int f = 0; f < 16; f++)
            #pragma unroll
            for (int r = 0; r < 4; r++) o[mi][f][r] = 0.f;
    float rs[2][2] = {{0.f, 0.f}, {0.f, 0.f}};

    for (int kt = 0; kt < 64; kt++) {
        int s = kt & 1;
        if (kt < 63) { load_kv(s ^ 1, kt + 1); cp_wait1(); } else cp_wait0();
        __syncthreads();

        // S = Q K^T  (32 q-rows per warp x 32 keys); log2e pre-folded into Q
        float fs[2][4][4];
        #pragma unroll
        for (int mi = 0; mi < 2; mi++)
            #pragma unroll
            for (int f = 0; f < 4; f++)
                #pragma unroll
                for (int r = 0; r < 4; r++) fs[mi][f][r] = 0.f;
        #pragma unroll
        for (int kd = 0; kd < 4; kd++) {
            uint32_t k0[4], k1[4];
            ldm4(k0, smem_u32(&Ks[s][(l & 15)][kd * 16 + (l >> 4) * 8]));
            ldm4(k1, smem_u32(&Ks[s][16 + (l & 15)][kd * 16 + (l >> 4) * 8]));
            #pragma unroll
            for (int mi = 0; mi < 2; mi++) {
                mma16816(fs[mi][0], qa[kd][mi], k0[0], k0[2]);
                mma16816(fs[mi][1], qa[kd][mi], k0[1], k0[3]);
                mma16816(fs[mi][2], qa[kd][mi], k1[0], k1[2]);
                mma16816(fs[mi][3], qa[kd][mi], k1[1], k1[3]);
            }
        }

        // P = 2^S; rowsum accumulate; repack as A fragments for P@V
        uint32_t pa[2][2][4];
        #pragma unroll
        for (int mi = 0; mi < 2; mi++) {
            #pragma unroll
            for (int g = 0; g < 2; g++) {
                float e0[4], e1[4];
                #pragma unroll
                for (int r = 0; r < 4; r++) {
                    e0[r] = ex2f(fs[mi][2 * g][r]);
                    e1[r] = ex2f(fs[mi][2 * g + 1][r]);
                }
                rs[mi][0] += e0[0] + e0[1] + e1[0] + e1[1];
                rs[mi][1] += e0[2] + e0[3] + e1[2] + e1[3];
                pa[mi][g][0] = packbf(e0[0], e0[1]);
                pa[mi][g][1] = packbf(e0[2], e0[3]);
                pa[mi][g][2] = packbf(e1[0], e1[1]);
                pa[mi][g][3] = packbf(e1[2], e1[3]);
            }
        }

        // O += P @ V  (V row-major [keys][cols] via trans-ldmatrix)
        #pragma unroll
        for (int g = 0; g < 2; g++) {
            #pragma unroll
            for (int nc = 0; nc < 8; nc++) {
                uint32_t vb[4];
                ldm4t(vb, smem_u32(&Vs[s][g * 16 + (l & 15)][nc * 16 + (l >> 4) * 8]));
                #pragma unroll
                for (int mi = 0; mi < 2; mi++) {
                    mma16816(o[mi][2 * nc],     pa[mi][g], vb[0], vb[1]);
                    mma16816(o[mi][2 * nc + 1], pa[mi][g], vb[2], vb[3]);
                }
            }
        }
        __syncthreads();
    }

    // reduce rowsums across the 4 lanes sharing each row
    #pragma unroll
    for (int mi = 0; mi < 2; mi++) {
        rs[mi][0] += __shfl_xor_sync(0xffffffffu, rs[mi][0], 1);
        rs[mi][0] += __shfl_xor_sync(0xffffffffu, rs[mi][0], 2);
        rs[mi][1] += __shfl_xor_sync(0xffffffffu, rs[mi][1], 1);
        rs[mi][1] += __shfl_xor_sync(0xffffffffu, rs[mi][1], 2);
    }
    const float gm = gamma[0];

    // epilogue: out = gamma * O / rowsum + x   ([B, N, C] fp32)
    #pragma unroll
    for (int mi = 0; mi < 2; mi++) {
        const float i0 = gm / rs[mi][0], i1 = gm / rs[mi][1];
        const int q0 = qt * 128 + w * 32 + mi * 16 + (l >> 2);
        const size_t base = ((size_t)(b * NN + q0)) * CC + vc * 128;
        #pragma unroll
        for (int f = 0; f < 16; f++) {
            const int n = f * 8 + ((l & 3) << 1);
            float2 xr0 = *reinterpret_cast<const float2*>(&x[base + n]);
            float2 ov0 = make_float2(o[mi][f][0] * i0 + xr0.x, o[mi][f][1] * i0 + xr0.y);
            *reinterpret_cast<float2*>(&out[base + n]) = ov0;
            float2 xr1 = *reinterpret_cast<const float2*>(&x[base + 8 * CC + n]);
            float2 ov1 = make_float2(o[mi][f][2] * i1 + xr1.x, o[mi][f][3] * i1 + xr1.y);
            *reinterpret_cast<float2*>(&out[base + 8 * CC + n]) = ov1;
        }
    }
}

// ---------------- launch ----------------
extern "C" void kernel_launch(void* const* d_in, const int* in_sizes, int n_in,
                              void* d_out, int out_size) {
    (void)in_sizes; (void)n_in; (void)out_size;
    const float* x     = (const float*)d_in[0];
    const float* Wq    = (const float*)d_in[1];
    const float* bq    = (const float*)d_in[2];
    const float* Wk    = (const float*)d_in[3];
    const float* bk    = (const float*)d_in[4];
    const float* Wv    = (const float*)d_in[5];
    const float* bv    = (const float*)d_in[6];
    const float* gamma = (const float*)d_in[7];
    float* out = (float*)d_out;

    k0_cvt_x<<<(int)(((size_t)MM * CC / 4 + 255) / 256), 256>>>(x);
    k0_cvt_w<<<(NOUT * CC + 255) / 256, 256>>>(Wq, bq, Wk, bk, Wv, bv);
    k1_qkv<<<dim3(NOUT / 128, MM / 128), 256>>>();
    k2_attn<<<dim3(CC / 128, NN / 128, BB), 128>>>(x, out, gamma);
}